// round 4
// baseline (speedup 1.0000x reference)
#include <cuda_runtime.h>
#include <stdint.h>

#define N_ROWS 16384
#define K_DIM  200
#define H_DIM  768
#define NB_AUG 10

// ---------------- scratch (static device globals; no allocations) ----------
__device__ float g_x[(size_t)N_ROWS * K_DIM];   // fc output
__device__ float g_mu[K_DIM];
__device__ float g_sd[K_DIM];                   // sqrt(var + 1e-5)

// ---------------- threefry2x32 (JAX-exact) ---------------------------------
__device__ __forceinline__ uint2 tf2x32(uint32_t k0, uint32_t k1,
                                        uint32_t x0, uint32_t x1) {
    uint32_t ks2 = k0 ^ k1 ^ 0x1BD11BDAu;
    x0 += k0; x1 += k1;
#define TFR(r) { x0 += x1; x1 = __funnelshift_l(x1, x1, (r)); x1 ^= x0; }
    TFR(13) TFR(15) TFR(26) TFR(6)
    x0 += k1;  x1 += ks2 + 1u;
    TFR(17) TFR(29) TFR(16) TFR(24)
    x0 += ks2; x1 += k0 + 2u;
    TFR(13) TFR(15) TFR(26) TFR(6)
    x0 += k0;  x1 += k1 + 3u;
    TFR(17) TFR(29) TFR(16) TFR(24)
    x0 += k1;  x1 += ks2 + 4u;
    TFR(13) TFR(15) TFR(26) TFR(6)
    x0 += ks2; x1 += k0 + 5u;
#undef TFR
    return make_uint2(x0, x1);
}

// bits -> float in [0,1): ((bits>>9)|0x3f800000) bitcast - 1.0
__device__ __forceinline__ float bits_to_f01(uint32_t bits) {
    return __fsub_rn(__uint_as_float((bits >> 9) | 0x3f800000u), 1.0f);
}

// ---------------- XLA/Giles erfinv (f32), no FMA contraction ---------------
__device__ __forceinline__ float erfinv_xla(float x) {
    float w = -log1pf(-__fmul_rn(x, x));
    float p;
    if (w < 5.0f) {
        w = __fsub_rn(w, 2.5f);
        p = 2.81022636e-08f;
        p = __fadd_rn( 3.43273939e-07f, __fmul_rn(p, w));
        p = __fadd_rn(-3.5233877e-06f,  __fmul_rn(p, w));
        p = __fadd_rn(-4.39150654e-06f, __fmul_rn(p, w));
        p = __fadd_rn( 0.00021858087f,  __fmul_rn(p, w));
        p = __fadd_rn(-0.00125372503f,  __fmul_rn(p, w));
        p = __fadd_rn(-0.00417768164f,  __fmul_rn(p, w));
        p = __fadd_rn( 0.246640727f,    __fmul_rn(p, w));
        p = __fadd_rn( 1.50140941f,     __fmul_rn(p, w));
    } else {
        w = __fsub_rn(sqrtf(w), 3.0f);
        p = -0.000200214257f;
        p = __fadd_rn( 0.000100950558f, __fmul_rn(p, w));
        p = __fadd_rn( 0.00134934322f,  __fmul_rn(p, w));
        p = __fadd_rn(-0.00367342844f,  __fmul_rn(p, w));
        p = __fadd_rn( 0.00573950773f,  __fmul_rn(p, w));
        p = __fadd_rn(-0.0076224613f,   __fmul_rn(p, w));
        p = __fadd_rn( 0.00943887047f,  __fmul_rn(p, w));
        p = __fadd_rn( 1.00167406f,     __fmul_rn(p, w));
        p = __fadd_rn( 2.83297682f,     __fmul_rn(p, w));
    }
    return __fmul_rn(p, x);
}

// scalar normal from a key (JAX: sqrt2 * erfinv(uniform(lo=-0.99999994, hi=1)))
__device__ __forceinline__ float jax_normal_from_key(uint2 k) {
    uint2 nb = tf2x32(k.x, k.y, 0u, 0u);
    float f = bits_to_f01(nb.x ^ nb.y);
    float u = fmaxf(-0.99999994f, __fadd_rn(__fmul_rn(f, 2.0f), -0.99999994f));
    return __fmul_rn(__uint_as_float(0x3FB504F3u) /* sqrt(2) f32 */, erfinv_xla(u));
}

// ---------------- JAX gamma sampler (Marsaglia-Tsang, alpha >= 1) ----------
// flat element index i: per-element key Ki = TF((0,42),(0,i))  [partitionable split]
__device__ float jax_gamma(float aB, uint32_t i) {
    uint2 Ki  = tf2x32(0u, 42u, 0u, i);
    uint2 key = tf2x32(Ki.x, Ki.y, 0u, 0u);

    float d = __fsub_rn(aB, 0.33333334f);
    float c = __fdiv_rn(0.33333334f, sqrtf(d));
    float V = 1.0f;

    for (;;) {
        uint2 xkey = tf2x32(key.x, key.y, 0u, 1u);
        uint2 Ukey = tf2x32(key.x, key.y, 0u, 2u);
        float x, v;
        uint2 ik = xkey;
        for (;;) {
            uint2 sub = tf2x32(ik.x, ik.y, 0u, 1u);
            x = jax_normal_from_key(sub);
            v = __fadd_rn(1.0f, __fmul_rn(x, c));
            if (v > 0.0f) break;
            ik = tf2x32(ik.x, ik.y, 0u, 0u);
        }
        float X = __fmul_rn(x, x);
        V = __fmul_rn(__fmul_rn(v, v), v);
        uint2 ub = tf2x32(Ukey.x, Ukey.y, 0u, 0u);
        float U = bits_to_f01(ub.x ^ ub.y);

        float sq = __fsub_rn(1.0f, __fmul_rn(0.0331f, __fmul_rn(X, X)));
        if (U < sq) break;
        float rhs = __fadd_rn(__fmul_rn(X, 0.5f),
                    __fadd_rn(__fsub_rn(d, __fmul_rn(d, V)), __fmul_rn(d, logf(V))));
        if (logf(U) < rhs) break;
        key = tf2x32(key.x, key.y, 0u, 0u);
    }
    float z = __fmul_rn(d, V);
    return (z == 0.0f) ? 1.17549435e-38f : z;
}

// ---------------- SGEMM -----------------------------------------------------
// 128x128 block tile, BK=16, double-buffered smem. Warp tiling: 8 warps as
// 2(m) x 4(n); warp tile 64x32; lanes 8(m) x 4(n); microtile 8x8.
// Smem uses 16B-chunk XOR swizzle (c ^= c>>3) so every fragment LDS.128 is
// bank-conflict-free (1 wavefront) -> 4 wf/warp/kk vs 10 before.
// Per-output FMA chain iterates k=0..767 monotonically with one accumulator
// => bitwise-identical x regardless of thread mapping (decision path safe).
__device__ __forceinline__ int swz_word(int m) {   // m: row 0..127 -> word in 128-word row
    int c = m >> 2;
    return ((c ^ (c >> 3)) << 2) + (m & 3);
}

__global__ void __launch_bounds__(256, 2)
gemm_kernel(const float* __restrict__ A, const float* __restrict__ Wm,
            const float* __restrict__ bias) {
    const int BM = 128, BN = 128, BK = 16;
    __shared__ float As[2][BK * BM];
    __shared__ float Bs[2][BK * BN];

    const int m0 = blockIdx.y * BM;
    const int n0 = blockIdx.x * BN;
    const int tid = threadIdx.x;
    const int w  = tid >> 5;
    const int l  = tid & 31;
    const int wm = w & 1;        // 0..1
    const int wn = w >> 1;       // 0..3
    const int ml = l & 7;        // 0..7
    const int nl = l >> 3;       // 0..3

    // fragment smem word offsets (swizzled chunk positions)
    const int cA0 = wm * 16 + ml * 2, cA1 = cA0 + 1;
    const int offA0 = ((cA0 ^ (cA0 >> 3)) << 2);
    const int offA1 = ((cA1 ^ (cA1 >> 3)) << 2);
    const int cB0 = wn * 8 + nl * 2, cB1 = cB0 + 1;
    const int offB0 = ((cB0 ^ (cB0 >> 3)) << 2);
    const int offB1 = ((cB1 ^ (cB1 >> 3)) << 2);

    // global-load mapping: thread loads 2 float4 of A and 2 of B per tile
    const int ra0 = (tid * 2) >> 2,     ca0 = (tid * 2) & 3;
    const int ra1 = (tid * 2 + 1) >> 2, ca1 = (tid * 2 + 1) & 3;
    const bool bv0ok = (n0 + ra0) < K_DIM;
    const bool bv1ok = (n0 + ra1) < K_DIM;

    float acc[8][8];
#pragma unroll
    for (int i = 0; i < 8; i++)
#pragma unroll
        for (int j = 0; j < 8; j++) acc[i][j] = 0.0f;

#define STS_SWZ(Sb, c4, r, v) do {                 \
        int w_ = swz_word(r);                      \
        (Sb)[((c4)*4 + 0) * 128 + w_] = (v).x;     \
        (Sb)[((c4)*4 + 1) * 128 + w_] = (v).y;     \
        (Sb)[((c4)*4 + 2) * 128 + w_] = (v).z;     \
        (Sb)[((c4)*4 + 3) * 128 + w_] = (v).w;     \
    } while (0)

    // ---- load tile 0 into buffer 0 ----
    {
        float4 a0 = *reinterpret_cast<const float4*>(&A[(size_t)(m0 + ra0) * H_DIM + ca0 * 4]);
        float4 a1 = *reinterpret_cast<const float4*>(&A[(size_t)(m0 + ra1) * H_DIM + ca1 * 4]);
        float4 b0 = make_float4(0.f,0.f,0.f,0.f), b1 = make_float4(0.f,0.f,0.f,0.f);
        if (bv0ok) b0 = *reinterpret_cast<const float4*>(&Wm[(size_t)(n0 + ra0) * H_DIM + ca0 * 4]);
        if (bv1ok) b1 = *reinterpret_cast<const float4*>(&Wm[(size_t)(n0 + ra1) * H_DIM + ca1 * 4]);
        STS_SWZ(As[0], ca0, ra0, a0);
        STS_SWZ(As[0], ca1, ra1, a1);
        STS_SWZ(Bs[0], ca0, ra0, b0);
        STS_SWZ(Bs[0], ca1, ra1, b1);
    }
    __syncthreads();

    int buf = 0;
    for (int t = 1; t <= H_DIM / BK; t++) {
        float4 a0, a1, b0, b1;
        const bool more = (t < H_DIM / BK);
        if (more) {
            const int h0 = t * BK;
            a0 = *reinterpret_cast<const float4*>(&A[(size_t)(m0 + ra0) * H_DIM + h0 + ca0 * 4]);
            a1 = *reinterpret_cast<const float4*>(&A[(size_t)(m0 + ra1) * H_DIM + h0 + ca1 * 4]);
            b0 = make_float4(0.f,0.f,0.f,0.f); b1 = make_float4(0.f,0.f,0.f,0.f);
            if (bv0ok) b0 = *reinterpret_cast<const float4*>(&Wm[(size_t)(n0 + ra0) * H_DIM + h0 + ca0 * 4]);
            if (bv1ok) b1 = *reinterpret_cast<const float4*>(&Wm[(size_t)(n0 + ra1) * H_DIM + h0 + ca1 * 4]);
        }
#pragma unroll
        for (int kk = 0; kk < BK; kk++) {
            const float* Ab = &As[buf][kk * BM];
            const float* Bb = &Bs[buf][kk * BN];
            float4 fa0 = *reinterpret_cast<const float4*>(Ab + offA0);
            float4 fa1 = *reinterpret_cast<const float4*>(Ab + offA1);
            float4 fb0 = *reinterpret_cast<const float4*>(Bb + offB0);
            float4 fb1 = *reinterpret_cast<const float4*>(Bb + offB1);
            float af[8] = {fa0.x, fa0.y, fa0.z, fa0.w, fa1.x, fa1.y, fa1.z, fa1.w};
            float bf[8] = {fb0.x, fb0.y, fb0.z, fb0.w, fb1.x, fb1.y, fb1.z, fb1.w};
#pragma unroll
            for (int i = 0; i < 8; i++)
#pragma unroll
                for (int j = 0; j < 8; j++)
                    acc[i][j] = fmaf(af[i], bf[j], acc[i][j]);
        }
        if (more) {
            int nb = buf ^ 1;
            STS_SWZ(As[nb], ca0, ra0, a0);
            STS_SWZ(As[nb], ca1, ra1, a1);
            STS_SWZ(Bs[nb], ca0, ra0, b0);
            STS_SWZ(Bs[nb], ca1, ra1, b1);
            __syncthreads();
            buf = nb;
        }
    }
#undef STS_SWZ

    const int mB  = m0 + wm * 64 + ml * 8;
    const int nnb = n0 + wn * 32 + nl * 8;
    if (nnb < K_DIM) {   // K_DIM % 8 == 0 so the whole 8-col group is in/out
        float4 bb0 = *reinterpret_cast<const float4*>(&bias[nnb]);
        float4 bb1 = *reinterpret_cast<const float4*>(&bias[nnb + 4]);
#pragma unroll
        for (int i = 0; i < 8; i++) {
            float4 v0 = make_float4(acc[i][0] + bb0.x, acc[i][1] + bb0.y,
                                    acc[i][2] + bb0.z, acc[i][3] + bb0.w);
            float4 v1 = make_float4(acc[i][4] + bb1.x, acc[i][5] + bb1.y,
                                    acc[i][6] + bb1.z, acc[i][7] + bb1.w);
            *reinterpret_cast<float4*>(&g_x[(size_t)(mB + i) * K_DIM + nnb])     = v0;
            *reinterpret_cast<float4*>(&g_x[(size_t)(mB + i) * K_DIM + nnb + 4]) = v1;
        }
    }
}

// ---------------- per-column mean / std (coalesced, exact order) ------------
// 25 blocks x 8 columns. 256-row tiles staged coalesced into smem (double
// buffered). Warp w owns column k0+w; lane l owns partials vt = l+32j.
// Reproduces EXACTLY the previous (passing) 256-partial order per column and
// the same sm[t]+=sm[t+st] tree pairing => bitwise-identical mu/sd.
__global__ void __launch_bounds__(256) colstats_kernel() {
    const int k0  = blockIdx.x * 8;
    const int tid = threadIdx.x;
    const int w   = tid >> 5;
    const int l   = tid & 31;

    __shared__ float tile[2][256][9];   // 9-pad: conflict-free column reads
    __shared__ float red[8][257];
    __shared__ float mus[8];

    auto stage = [&](int T, int b) {
#pragma unroll
        for (int q = 0; q < 8; q++) {
            int e = q * 256 + tid;
            int r = e >> 3, c = e & 7;
            tile[b][r][c] = g_x[(size_t)(T * 256 + r) * K_DIM + k0 + c];
        }
    };

    // ---- pass 1: mean ----
    float p[8];
#pragma unroll
    for (int j = 0; j < 8; j++) p[j] = 0.0f;

    stage(0, 0);
    __syncthreads();
    for (int T = 0; T < 64; T++) {
        int cur = T & 1;
        if (T + 1 < 64) stage(T + 1, cur ^ 1);
#pragma unroll
        for (int j = 0; j < 8; j++) p[j] += tile[cur][l + 32 * j][w];
        __syncthreads();
    }
#pragma unroll
    for (int j = 0; j < 8; j++) red[w][l + 32 * j] = p[j];
    __syncthreads();
    for (int st = 128; st > 0; st >>= 1) {
        for (int idx = tid; idx < 8 * st; idx += 256) {
            int c = idx / st, t2 = idx - c * st;
            red[c][t2] += red[c][t2 + st];
        }
        __syncthreads();
    }
    if (tid < 8) mus[tid] = red[tid][0] / 16384.0f;
    __syncthreads();

    // ---- pass 2: variance ----
    const float mu = mus[w];
#pragma unroll
    for (int j = 0; j < 8; j++) p[j] = 0.0f;

    stage(0, 0);
    __syncthreads();
    for (int T = 0; T < 64; T++) {
        int cur = T & 1;
        if (T + 1 < 64) stage(T + 1, cur ^ 1);
#pragma unroll
        for (int j = 0; j < 8; j++) {
            float dd = tile[cur][l + 32 * j][w] - mu;
            p[j] += dd * dd;
        }
        __syncthreads();
    }
#pragma unroll
    for (int j = 0; j < 8; j++) red[w][l + 32 * j] = p[j];
    __syncthreads();
    for (int st = 128; st > 0; st >>= 1) {
        for (int idx = tid; idx < 8 * st; idx += 256) {
            int c = idx / st, t2 = idx - c * st;
            red[c][t2] += red[c][t2 + st];
        }
        __syncthreads();
    }
    if (tid < 8) {
        g_mu[k0 + tid] = mus[tid];
        g_sd[k0 + tid] = sqrtf(red[tid][0] / 16384.0f + 1e-5f);
    }
}

// ---------------- fused: softplus -> gamma -> u-pow product -> rownorm -----
// 224 threads/row (7 warps, 89% lane efficiency). Reduction tree values are
// bitwise-identical to the 256-thread version (sm[200..255] are zeros).
__global__ void __launch_bounds__(224)
main_kernel(const float* __restrict__ u, float* __restrict__ out) {
    int n = blockIdx.x;
    int k = threadIdx.x;
    float g = 0.0f;

    if (k < K_DIM) {
        float xv = g_x[(size_t)n * K_DIM + k];
        float xn = __fdiv_rn(__fsub_rn(xv, g_mu[k]), g_sd[k]);
        // softplus = max(x,0) + log1p(exp(-|x|))   (decision path: exact)
        float sp = __fadd_rn(fmaxf(xn, 0.0f), log1pf(expf(-fabsf(xn))));
        float alphas = fmaxf(1e-5f, sp);
        float aB = __fadd_rn(alphas, 10.0f);

        uint32_t flat = (uint32_t)n * K_DIM + (uint32_t)k;
        float gam = jax_gamma(aB, flat);

        float prod = 1.0f;
#pragma unroll
        for (int r = 0; r < NB_AUG; r++) {
            float uu = u[(size_t)r * N_ROWS * K_DIM + (size_t)n * K_DIM + k];
            float av = __fadd_rn(alphas, (float)r);
            float up = __fadd_rn(__powf(uu, __fdividef(1.0f, av)), 1e-10f);
            prod = __fmul_rn(prod, up);
        }
        g = __fmul_rn(prod, gam);
    }

    __shared__ float sm[256];
    sm[threadIdx.x] = g;
    if (threadIdx.x < 32) sm[224 + threadIdx.x] = 0.0f;
    __syncthreads();
    for (int st = 128; st > 0; st >>= 1) {
        if (threadIdx.x < st) sm[threadIdx.x] += sm[threadIdx.x + st];
        __syncthreads();
    }
    float rowsum = sm[0];

    if (k < K_DIM)
        out[(size_t)n * K_DIM + k] = __fdiv_rn(g, rowsum);
}

// ---------------- launcher --------------------------------------------------
extern "C" void kernel_launch(void* const* d_in, const int* in_sizes, int n_in,
                              void* d_out, int out_size) {
    const float* hidden = (const float*)d_in[0];   // [16384, 768]
    const float* W      = (const float*)d_in[1];   // [200, 768]
    const float* bias   = (const float*)d_in[2];   // [200]
    const float* u      = (const float*)d_in[3];   // [10, 16384, 200]
    float* out = (float*)d_out;                    // [16384, 200]

    dim3 ggrid((K_DIM + 127) / 128, N_ROWS / 128); // (2, 128)
    gemm_kernel<<<ggrid, 256>>>(hidden, W, bias);
    colstats_kernel<<<25, 256>>>();
    main_kernel<<<N_ROWS, 224>>>(u, out);
}

// round 6
// speedup vs baseline: 1.0463x; 1.0463x over previous
#include <cuda_runtime.h>
#include <stdint.h>

#define N_ROWS 16384
#define K_DIM  200
#define H_DIM  768
#define NB_AUG 10

// ---------------- scratch (static device globals; no allocations) ----------
__device__ float g_x [(size_t)N_ROWS * K_DIM];   // fc output [N][K]
__device__ float g_xT[(size_t)K_DIM * N_ROWS];   // transposed [K][N]
__device__ float g_mu[K_DIM];
__device__ float g_sd[K_DIM];                    // sqrt(var + 1e-5)

// ---------------- threefry2x32 (JAX-exact) ---------------------------------
__device__ __forceinline__ uint2 tf2x32(uint32_t k0, uint32_t k1,
                                        uint32_t x0, uint32_t x1) {
    uint32_t ks2 = k0 ^ k1 ^ 0x1BD11BDAu;
    x0 += k0; x1 += k1;
#define TFR(r) { x0 += x1; x1 = __funnelshift_l(x1, x1, (r)); x1 ^= x0; }
    TFR(13) TFR(15) TFR(26) TFR(6)
    x0 += k1;  x1 += ks2 + 1u;
    TFR(17) TFR(29) TFR(16) TFR(24)
    x0 += ks2; x1 += k0 + 2u;
    TFR(13) TFR(15) TFR(26) TFR(6)
    x0 += k0;  x1 += k1 + 3u;
    TFR(17) TFR(29) TFR(16) TFR(24)
    x0 += k1;  x1 += ks2 + 4u;
    TFR(13) TFR(15) TFR(26) TFR(6)
    x0 += ks2; x1 += k0 + 5u;
#undef TFR
    return make_uint2(x0, x1);
}

__device__ __forceinline__ float bits_to_f01(uint32_t bits) {
    return __fsub_rn(__uint_as_float((bits >> 9) | 0x3f800000u), 1.0f);
}

// ---------------- XLA/Giles erfinv (f32), no FMA contraction ---------------
__device__ __forceinline__ float erfinv_xla(float x) {
    float w = -log1pf(-__fmul_rn(x, x));
    float p;
    if (w < 5.0f) {
        w = __fsub_rn(w, 2.5f);
        p = 2.81022636e-08f;
        p = __fadd_rn( 3.43273939e-07f, __fmul_rn(p, w));
        p = __fadd_rn(-3.5233877e-06f,  __fmul_rn(p, w));
        p = __fadd_rn(-4.39150654e-06f, __fmul_rn(p, w));
        p = __fadd_rn( 0.00021858087f,  __fmul_rn(p, w));
        p = __fadd_rn(-0.00125372503f,  __fmul_rn(p, w));
        p = __fadd_rn(-0.00417768164f,  __fmul_rn(p, w));
        p = __fadd_rn( 0.246640727f,    __fmul_rn(p, w));
        p = __fadd_rn( 1.50140941f,     __fmul_rn(p, w));
    } else {
        w = __fsub_rn(sqrtf(w), 3.0f);
        p = -0.000200214257f;
        p = __fadd_rn( 0.000100950558f, __fmul_rn(p, w));
        p = __fadd_rn( 0.00134934322f,  __fmul_rn(p, w));
        p = __fadd_rn(-0.00367342844f,  __fmul_rn(p, w));
        p = __fadd_rn( 0.00573950773f,  __fmul_rn(p, w));
        p = __fadd_rn(-0.0076224613f,   __fmul_rn(p, w));
        p = __fadd_rn( 0.00943887047f,  __fmul_rn(p, w));
        p = __fadd_rn( 1.00167406f,     __fmul_rn(p, w));
        p = __fadd_rn( 2.83297682f,     __fmul_rn(p, w));
    }
    return __fmul_rn(p, x);
}

__device__ __forceinline__ float jax_normal_from_key(uint2 k) {
    uint2 nb = tf2x32(k.x, k.y, 0u, 0u);
    float f = bits_to_f01(nb.x ^ nb.y);
    float u = fmaxf(-0.99999994f, __fadd_rn(__fmul_rn(f, 2.0f), -0.99999994f));
    return __fmul_rn(__uint_as_float(0x3FB504F3u), erfinv_xla(u));
}

// ---------------- JAX gamma sampler (Marsaglia-Tsang, alpha >= 1) ----------
__device__ float jax_gamma(float aB, uint32_t i) {
    uint2 Ki  = tf2x32(0u, 42u, 0u, i);
    uint2 key = tf2x32(Ki.x, Ki.y, 0u, 0u);

    float d = __fsub_rn(aB, 0.33333334f);
    float c = __fdiv_rn(0.33333334f, sqrtf(d));
    float V = 1.0f;

    for (;;) {
        uint2 xkey = tf2x32(key.x, key.y, 0u, 1u);
        uint2 Ukey = tf2x32(key.x, key.y, 0u, 2u);
        float x, v;
        uint2 ik = xkey;
        for (;;) {
            uint2 sub = tf2x32(ik.x, ik.y, 0u, 1u);
            x = jax_normal_from_key(sub);
            v = __fadd_rn(1.0f, __fmul_rn(x, c));
            if (v > 0.0f) break;
            ik = tf2x32(ik.x, ik.y, 0u, 0u);
        }
        float X = __fmul_rn(x, x);
        V = __fmul_rn(__fmul_rn(v, v), v);
        uint2 ub = tf2x32(Ukey.x, Ukey.y, 0u, 0u);
        float U = bits_to_f01(ub.x ^ ub.y);

        float sq = __fsub_rn(1.0f, __fmul_rn(0.0331f, __fmul_rn(X, X)));
        if (U < sq) break;
        float rhs = __fadd_rn(__fmul_rn(X, 0.5f),
                    __fadd_rn(__fsub_rn(d, __fmul_rn(d, V)), __fmul_rn(d, logf(V))));
        if (logf(U) < rhs) break;
        key = tf2x32(key.x, key.y, 0u, 0u);
    }
    float z = __fmul_rn(d, V);
    return (z == 0.0f) ? 1.17549435e-38f : z;
}

// ---------------- SGEMM -----------------------------------------------------
// 64x128 block tile, BK=16, double-buffered smem. 8 warps as 2(m) x 4(n);
// warp tile 32x32; lanes 8(m) x 4(n); microtile 4x8. ~76 regs -> 3 blocks/SM
// (24 warps). grid=512 -> balanced 3.46 blocks/SM, no tail wave.
// Per-output FMA chain iterates k=0..767 monotonically with one accumulator
// => bitwise-identical x (decision path safe).
__device__ __forceinline__ int swz_word128(int m) {  // row of 128 words
    int c = m >> 2;
    return ((c ^ (c >> 3)) << 2) + (m & 3);
}

__global__ void __launch_bounds__(256, 3)
gemm_kernel(const float* __restrict__ A, const float* __restrict__ Wm,
            const float* __restrict__ bias) {
    const int BM = 64, BN = 128, BK = 16;
    __shared__ float As[2][BK * BM];
    __shared__ float Bs[2][BK * BN];

    const int m0 = blockIdx.y * BM;
    const int n0 = blockIdx.x * BN;
    const int tid = threadIdx.x;
    const int w  = tid >> 5;
    const int l  = tid & 31;
    const int wm = w & 1;        // 0..1
    const int wn = w >> 1;       // 0..3
    const int ml = l & 7;        // 0..7
    const int nl = l >> 3;       // 0..3

    // fragment offsets
    const int offA = wm * 32 + ml * 4;                 // A row is 64 words, no swizzle
    const int cB0 = wn * 8 + nl * 2, cB1 = cB0 + 1;
    const int offB0 = ((cB0 ^ (cB0 >> 3)) << 2);
    const int offB1 = ((cB1 ^ (cB1 >> 3)) << 2);

    // global-load mapping
    const int rA  = tid >> 2,            cA4 = tid & 3;          // A: 1 float4/thread
    const int ra0 = (tid * 2) >> 2,      ca0 = (tid * 2) & 3;    // B: 2 float4/thread
    const int ra1 = (tid * 2 + 1) >> 2,  ca1 = (tid * 2 + 1) & 3;
    const bool bv0ok = (n0 + ra0) < K_DIM;
    const bool bv1ok = (n0 + ra1) < K_DIM;

    float acc[4][8];
#pragma unroll
    for (int i = 0; i < 4; i++)
#pragma unroll
        for (int j = 0; j < 8; j++) acc[i][j] = 0.0f;

#define STS_A(Sb, v) do {                              \
        (Sb)[((cA4)*4 + 0) * 64 + rA] = (v).x;         \
        (Sb)[((cA4)*4 + 1) * 64 + rA] = (v).y;         \
        (Sb)[((cA4)*4 + 2) * 64 + rA] = (v).z;         \
        (Sb)[((cA4)*4 + 3) * 64 + rA] = (v).w;         \
    } while (0)
#define STS_B(Sb, c4, r, v) do {                       \
        int w_ = swz_word128(r);                       \
        (Sb)[((c4)*4 + 0) * 128 + w_] = (v).x;         \
        (Sb)[((c4)*4 + 1) * 128 + w_] = (v).y;         \
        (Sb)[((c4)*4 + 2) * 128 + w_] = (v).z;         \
        (Sb)[((c4)*4 + 3) * 128 + w_] = (v).w;         \
    } while (0)

    // ---- load tile 0 into buffer 0 ----
    {
        float4 av = *reinterpret_cast<const float4*>(&A[(size_t)(m0 + rA) * H_DIM + cA4 * 4]);
        float4 b0 = make_float4(0.f,0.f,0.f,0.f), b1 = make_float4(0.f,0.f,0.f,0.f);
        if (bv0ok) b0 = *reinterpret_cast<const float4*>(&Wm[(size_t)(n0 + ra0) * H_DIM + ca0 * 4]);
        if (bv1ok) b1 = *reinterpret_cast<const float4*>(&Wm[(size_t)(n0 + ra1) * H_DIM + ca1 * 4]);
        STS_A(As[0], av);
        STS_B(Bs[0], ca0, ra0, b0);
        STS_B(Bs[0], ca1, ra1, b1);
    }
    __syncthreads();

    int buf = 0;
    for (int t = 1; t <= H_DIM / BK; t++) {
        float4 av, b0, b1;
        const bool more = (t < H_DIM / BK);
        if (more) {
            const int h0 = t * BK;
            av = *reinterpret_cast<const float4*>(&A[(size_t)(m0 + rA) * H_DIM + h0 + cA4 * 4]);
            b0 = make_float4(0.f,0.f,0.f,0.f); b1 = make_float4(0.f,0.f,0.f,0.f);
            if (bv0ok) b0 = *reinterpret_cast<const float4*>(&Wm[(size_t)(n0 + ra0) * H_DIM + h0 + ca0 * 4]);
            if (bv1ok) b1 = *reinterpret_cast<const float4*>(&Wm[(size_t)(n0 + ra1) * H_DIM + h0 + ca1 * 4]);
        }
#pragma unroll
        for (int kk = 0; kk < BK; kk++) {
            const float* Ab = &As[buf][kk * BM];
            const float* Bb = &Bs[buf][kk * BN];
            float4 fa  = *reinterpret_cast<const float4*>(Ab + offA);
            float4 fb0 = *reinterpret_cast<const float4*>(Bb + offB0);
            float4 fb1 = *reinterpret_cast<const float4*>(Bb + offB1);
            float af[4] = {fa.x, fa.y, fa.z, fa.w};
            float bf[8] = {fb0.x, fb0.y, fb0.z, fb0.w, fb1.x, fb1.y, fb1.z, fb1.w};
#pragma unroll
            for (int i = 0; i < 4; i++)
#pragma unroll
                for (int j = 0; j < 8; j++)
                    acc[i][j] = fmaf(af[i], bf[j], acc[i][j]);
        }
        if (more) {
            int nb = buf ^ 1;
            STS_A(As[nb], av);
            STS_B(Bs[nb], ca0, ra0, b0);
            STS_B(Bs[nb], ca1, ra1, b1);
            __syncthreads();
            buf = nb;
        }
    }
#undef STS_A
#undef STS_B

    const int mB  = m0 + wm * 32 + ml * 4;
    const int nnb = n0 + wn * 32 + nl * 8;
    if (nnb < K_DIM) {   // K_DIM % 8 == 0: whole 8-col group in/out together
        float4 bb0 = *reinterpret_cast<const float4*>(&bias[nnb]);
        float4 bb1 = *reinterpret_cast<const float4*>(&bias[nnb + 4]);
#pragma unroll
        for (int i = 0; i < 4; i++) {
            float4 v0 = make_float4(acc[i][0] + bb0.x, acc[i][1] + bb0.y,
                                    acc[i][2] + bb0.z, acc[i][3] + bb0.w);
            float4 v1 = make_float4(acc[i][4] + bb1.x, acc[i][5] + bb1.y,
                                    acc[i][6] + bb1.z, acc[i][7] + bb1.w);
            *reinterpret_cast<float4*>(&g_x[(size_t)(mB + i) * K_DIM + nnb])     = v0;
            *reinterpret_cast<float4*>(&g_x[(size_t)(mB + i) * K_DIM + nnb + 4]) = v1;
        }
    }
}

// ---------------- transpose g_x [N][K] -> g_xT [K][N] (coalesced both ways) -
__global__ void __launch_bounds__(256) transpose_kernel() {
    __shared__ float tile[32][33];
    const int k0 = blockIdx.x * 32;
    const int n0 = blockIdx.y * 32;
    const int tx = threadIdx.x & 31;
    const int ty = threadIdx.x >> 5;      // 0..7
#pragma unroll
    for (int q = 0; q < 4; q++) {
        int n = n0 + ty + q * 8;
        int k = k0 + tx;
        float v = 0.0f;
        if (k < K_DIM) v = g_x[(size_t)n * K_DIM + k];
        tile[ty + q * 8][tx] = v;
    }
    __syncthreads();
#pragma unroll
    for (int q = 0; q < 4; q++) {
        int k = k0 + ty + q * 8;
        int n = n0 + tx;
        if (k < K_DIM) g_xT[(size_t)k * N_ROWS + n] = tile[tx][ty + q * 8];
    }
}

// ---------------- per-column mean / std ------------------------------------
// One block per column, reading the transposed row (coalesced). Partial t
// sums n = t + 256*j in ascending j, then the sm[t]+=sm[t+st] tree -- the
// EXACT order of the original passing version => bitwise-identical mu/sd.
__global__ void __launch_bounds__(256) colstats_kernel() {
    const int k = blockIdx.x;
    const int t = threadIdx.x;
    const float* __restrict__ row = &g_xT[(size_t)k * N_ROWS];
    __shared__ float sm[256];

    float s = 0.0f;
    for (int j = 0; j < 64; j++) s += row[j * 256 + t];
    sm[t] = s; __syncthreads();
    for (int st = 128; st > 0; st >>= 1) {
        if (t < st) sm[t] += sm[t + st];
        __syncthreads();
    }
    float mu = sm[0] / 16384.0f;
    __syncthreads();

    float v = 0.0f;
    for (int j = 0; j < 64; j++) {
        float dd = row[j * 256 + t] - mu;
        v += dd * dd;
    }
    sm[t] = v; __syncthreads();
    for (int st = 128; st > 0; st >>= 1) {
        if (t < st) sm[t] += sm[t + st];
        __syncthreads();
    }
    if (t == 0) {
        g_mu[k] = mu;
        g_sd[k] = sqrtf(sm[0] / 16384.0f + 1e-5f);
    }
}

// ---------------- fused: softplus -> gamma -> u-pow product -> rownorm -----
__global__ void __launch_bounds__(224)
main_kernel(const float* __restrict__ u, float* __restrict__ out) {
    int n = blockIdx.x;
    int k = threadIdx.x;
    float g = 0.0f;

    if (k < K_DIM) {
        float xv = g_x[(size_t)n * K_DIM + k];
        float xn = __fdiv_rn(__fsub_rn(xv, g_mu[k]), g_sd[k]);
        float sp = __fadd_rn(fmaxf(xn, 0.0f), log1pf(expf(-fabsf(xn))));
        float alphas = fmaxf(1e-5f, sp);
        float aB = __fadd_rn(alphas, 10.0f);

        uint32_t flat = (uint32_t)n * K_DIM + (uint32_t)k;
        float gam = jax_gamma(aB, flat);

        float prod = 1.0f;
#pragma unroll
        for (int r = 0; r < NB_AUG; r++) {
            float uu = u[(size_t)r * N_ROWS * K_DIM + (size_t)n * K_DIM + k];
            float av = __fadd_rn(alphas, (float)r);
            float up = __fadd_rn(__powf(uu, __fdividef(1.0f, av)), 1e-10f);
            prod = __fmul_rn(prod, up);
        }
        g = __fmul_rn(prod, gam);
    }

    __shared__ float sm[256];
    sm[threadIdx.x] = g;
    if (threadIdx.x < 32) sm[224 + threadIdx.x] = 0.0f;
    __syncthreads();
    for (int st = 128; st > 0; st >>= 1) {
        if (threadIdx.x < st) sm[threadIdx.x] += sm[threadIdx.x + st];
        __syncthreads();
    }
    float rowsum = sm[0];

    if (k < K_DIM)
        out[(size_t)n * K_DIM + k] = __fdiv_rn(g, rowsum);
}

// ---------------- launcher --------------------------------------------------
extern "C" void kernel_launch(void* const* d_in, const int* in_sizes, int n_in,
                              void* d_out, int out_size) {
    const float* hidden = (const float*)d_in[0];   // [16384, 768]
    const float* W      = (const float*)d_in[1];   // [200, 768]
    const float* bias   = (const float*)d_in[2];   // [200]
    const float* u      = (const float*)d_in[3];   // [10, 16384, 200]
    float* out = (float*)d_out;                    // [16384, 200]

    dim3 ggrid((K_DIM + 127) / 128, N_ROWS / 64);  // (2, 256) = 512 blocks
    gemm_kernel<<<ggrid, 256>>>(hidden, W, bias);
    transpose_kernel<<<dim3(7, 512), 256>>>();
    colstats_kernel<<<K_DIM, 256>>>();
    main_kernel<<<N_ROWS, 224>>>(u, out);
}